// round 6
// baseline (speedup 1.0000x reference)
#include <cuda_runtime.h>

// Problem constants
#define B_  64
#define H_  128
#define W_  128
#define R_  4
#define GW_ 32
#define N_  1024   // GH*GW
#define D_  16
#define S_  32

#define QROW 17    // padded smem row stride (floats) -> conflict-free

// One block per n, 256 threads, >=6 CTAs/SM.
// Warp w owns quads w*16..w*16+15 (quad = (d,s4), 64 floats of pesos) and ALL
// 64 batches: lane l -> quad m=l&15, batch parity u=l>>4 (b = 2*bi+u).
//
// Weight extraction is WARP-LOCAL and fully coalesced: op j loads 512B
// contiguous (quads 2j,2j+1); the diagonal element m of quad 2j+u lands in
// lane 16u+m at float4 component l&3. Lanes stage their diag in padded smem,
// __syncwarp, then read their own quad's 16 weights conflict-free. The block
// __syncthreads gates only the 1KB xd staging (weight LDGs already in
// flight), so warps enter the store loop independently.
__global__ void __launch_bounds__(256, 6) conexao_kernel(
    const float* __restrict__ x, const float* __restrict__ pesos,
    float* __restrict__ out) {

    const int n = blockIdx.x;          // 0..1023
    const int t = threadIdx.x;
    const int w = t >> 5;
    const int l = t & 31;
    const int u = l >> 4;              // batch parity
    const int m = l & 15;              // this lane's quad within warp
    const int c = l & 3;               // float4 component holding the diag

    __shared__ float xds[B_ * R_];             // 1 KiB
    __shared__ float wsm[8][16 * QROW];        // 8 warps x 272 floats (~8.7 KB)

    // Warp's 16 quads start at float offset n*8192 + w*1024
    const float4* pv = reinterpret_cast<const float4*>(
        pesos + (size_t)n * (D_ * S_ * R_ * R_) + w * (16 * 64));

    // Weight LDG batch 1 (ops 0..3): 512B contiguous per op
    float4 v0 = __ldg(pv + 0 * 32 + l);
    float4 v1 = __ldg(pv + 1 * 32 + l);
    float4 v2 = __ldg(pv + 2 * 32 + l);
    float4 v3 = __ldg(pv + 3 * 32 + l);

    // xd extraction: one element per thread (256 = B*R)
    {
        const int b = t >> 2, r = t & 3;
        const int i = n >> 5, j = n & (GW_ - 1);
        xds[t] = __ldg(x + (size_t)b * (H_ * W_)
                         + (i * R_ + r) * W_ + (j * R_ + r));
    }
    __syncthreads();   // gates xds only; weight loads still in flight

    // Extract diag of batch 1: op j holds diag m of quad 2j+u at comp c
    #define PICK(v) (c == 0 ? (v).x : c == 1 ? (v).y : c == 2 ? (v).z : (v).w)
    wsm[w][(0 + u) * QROW + m] = PICK(v0);
    wsm[w][(2 + u) * QROW + m] = PICK(v1);
    wsm[w][(4 + u) * QROW + m] = PICK(v2);
    wsm[w][(6 + u) * QROW + m] = PICK(v3);

    // Weight LDG batch 2 (ops 4..7)
    v0 = __ldg(pv + 4 * 32 + l);
    v1 = __ldg(pv + 5 * 32 + l);
    v2 = __ldg(pv + 6 * 32 + l);
    v3 = __ldg(pv + 7 * 32 + l);
    wsm[w][(8  + u) * QROW + m] = PICK(v0);
    wsm[w][(10 + u) * QROW + m] = PICK(v1);
    wsm[w][(12 + u) * QROW + m] = PICK(v2);
    wsm[w][(14 + u) * QROW + m] = PICK(v3);
    #undef PICK

    __syncwarp();

    // This lane's 16 weights (row m, stride QROW -> conflict-free, 2-lane bcast)
    float wr[4][4];
    #pragma unroll
    for (int ss = 0; ss < 4; ss++)
        #pragma unroll
        for (int r = 0; r < 4; r++)
            wr[ss][r] = wsm[w][m * QROW + ss * 4 + r];

    // Store loop: 32 iters, b = 2*bi + u. Warp-op writes 512B contiguous.
    const float4* xdv = reinterpret_cast<const float4*>(xds);
    float4* o = reinterpret_cast<float4*>(out)
              + (size_t)u * (N_ * D_ * S_ / 4)
              + n * (D_ * S_ / 4) + w * 16 + m;
    const size_t ostr = (size_t)2 * N_ * (D_ * S_ / 4);   // per-bi stride

    #pragma unroll 8
    for (int bi = 0; bi < 32; bi++) {
        float4 xv = xdv[2 * bi + u];   // 2-address LDS broadcast
        float4 ov;
        ov.x = xv.x * wr[0][0] + xv.y * wr[0][1] + xv.z * wr[0][2] + xv.w * wr[0][3];
        ov.y = xv.x * wr[1][0] + xv.y * wr[1][1] + xv.z * wr[1][2] + xv.w * wr[1][3];
        ov.z = xv.x * wr[2][0] + xv.y * wr[2][1] + xv.z * wr[2][2] + xv.w * wr[2][3];
        ov.w = xv.x * wr[3][0] + xv.y * wr[3][1] + xv.z * wr[3][2] + xv.w * wr[3][3];
        __stcs(o + (size_t)bi * ostr, ov);   // evict-first streaming store
    }
}

extern "C" void kernel_launch(void* const* d_in, const int* in_sizes, int n_in,
                              void* d_out, int out_size) {
    const float* x     = (const float*)d_in[0];   // [64,1,128,128]
    const float* pesos = (const float*)d_in[1];   // [1024,16,32,4,4]
    float* out = (float*)d_out;                   // [64,1024,16,32]

    conexao_kernel<<<N_, 256>>>(x, pesos, out);
}

// round 7
// speedup vs baseline: 1.0011x; 1.0011x over previous
#include <cuda_runtime.h>

// Problem constants
#define B_  64
#define H_  128
#define W_  128
#define R_  4
#define GW_ 32
#define N_  1024   // GH*GW
#define D_  16
#define S_  32

#define QROW 17    // padded smem row stride (floats) -> conflict-free

// One block per n, 256 threads, 7 CTAs/SM -> 1036 resident CTAs >= 1024:
// the ENTIRE grid runs as a single wave (no tail).
//
// Warp w owns quads w*16..w*16+15 (quad = (d,s4), 64 floats of pesos) and ALL
// 64 batches: lane l -> quad m=l&15, batch parity u=l>>4 (b = 2*bi+u).
// Weight extraction is warp-local and fully coalesced (512B per warp-op);
// diag element m of quad 2j+u lands in lane 16u+m at component l&3.
// Loads issued in 2-deep batches to keep live regs <= 36 (7 CTA/SM cap).
__global__ void __launch_bounds__(256, 7) conexao_kernel(
    const float* __restrict__ x, const float* __restrict__ pesos,
    float* __restrict__ out) {

    const int n = blockIdx.x;          // 0..1023
    const int t = threadIdx.x;
    const int w = t >> 5;
    const int l = t & 31;
    const int u = l >> 4;              // batch parity
    const int m = l & 15;              // this lane's quad within warp
    const int c = l & 3;               // float4 component holding the diag

    __shared__ float xds[B_ * R_];             // 1 KiB
    __shared__ float wsm[8][16 * QROW];        // ~8.7 KB

    // Warp's 16 quads start at float offset n*8192 + w*1024
    const float4* pv = reinterpret_cast<const float4*>(
        pesos + (size_t)n * (D_ * S_ * R_ * R_) + w * (16 * 64));

    #define PICK(v) (c == 0 ? (v).x : c == 1 ? (v).y : c == 2 ? (v).z : (v).w)

    // Weight extraction: 4 batches of 2 float4 loads (8 live regs max)
    {
        float4 v0 = __ldg(pv + 0 * 32 + l);
        float4 v1 = __ldg(pv + 1 * 32 + l);

        // xd extraction overlapped with first weight batch (256 = B*R)
        const int b = t >> 2, r = t & 3;
        const int i = n >> 5, j = n & (GW_ - 1);
        xds[t] = __ldg(x + (size_t)b * (H_ * W_)
                         + (i * R_ + r) * W_ + (j * R_ + r));

        wsm[w][(0 + u) * QROW + m] = PICK(v0);
        wsm[w][(2 + u) * QROW + m] = PICK(v1);
    }
    {
        float4 v0 = __ldg(pv + 2 * 32 + l);
        float4 v1 = __ldg(pv + 3 * 32 + l);
        wsm[w][(4 + u) * QROW + m] = PICK(v0);
        wsm[w][(6 + u) * QROW + m] = PICK(v1);
    }
    {
        float4 v0 = __ldg(pv + 4 * 32 + l);
        float4 v1 = __ldg(pv + 5 * 32 + l);
        wsm[w][(8  + u) * QROW + m] = PICK(v0);
        wsm[w][(10 + u) * QROW + m] = PICK(v1);
    }
    {
        float4 v0 = __ldg(pv + 6 * 32 + l);
        float4 v1 = __ldg(pv + 7 * 32 + l);
        wsm[w][(12 + u) * QROW + m] = PICK(v0);
        wsm[w][(14 + u) * QROW + m] = PICK(v1);
    }
    #undef PICK

    __syncthreads();   // covers xds (block-wide) and wsm (warp-local)

    // This lane's 16 weights (row m, stride QROW -> conflict-free, 2-lane bcast)
    float wr[4][4];
    #pragma unroll
    for (int ss = 0; ss < 4; ss++)
        #pragma unroll
        for (int r = 0; r < 4; r++)
            wr[ss][r] = wsm[w][m * QROW + ss * 4 + r];

    // Store loop: 32 iters, b = 2*bi + u. Warp-op writes 512B contiguous.
    const float4* xdv = reinterpret_cast<const float4*>(xds);
    float4* o = reinterpret_cast<float4*>(out)
              + (size_t)u * (N_ * D_ * S_ / 4)
              + n * (D_ * S_ / 4) + w * 16 + m;
    const size_t ostr = (size_t)2 * N_ * (D_ * S_ / 4);   // per-bi stride

    #pragma unroll 8
    for (int bi = 0; bi < 32; bi++) {
        float4 xv = xdv[2 * bi + u];   // 2-address LDS broadcast
        float4 ov;
        ov.x = xv.x * wr[0][0] + xv.y * wr[0][1] + xv.z * wr[0][2] + xv.w * wr[0][3];
        ov.y = xv.x * wr[1][0] + xv.y * wr[1][1] + xv.z * wr[1][2] + xv.w * wr[1][3];
        ov.z = xv.x * wr[2][0] + xv.y * wr[2][1] + xv.z * wr[2][2] + xv.w * wr[2][3];
        ov.w = xv.x * wr[3][0] + xv.y * wr[3][1] + xv.z * wr[3][2] + xv.w * wr[3][3];
        __stcs(o + (size_t)bi * ostr, ov);   // evict-first streaming store
    }
}

extern "C" void kernel_launch(void* const* d_in, const int* in_sizes, int n_in,
                              void* d_out, int out_size) {
    const float* x     = (const float*)d_in[0];   // [64,1,128,128]
    const float* pesos = (const float*)d_in[1];   // [1024,16,32,4,4]
    float* out = (float*)d_out;                   // [64,1024,16,32]

    conexao_kernel<<<N_, 256>>>(x, pesos, out);
}